// round 4
// baseline (speedup 1.0000x reference)
#include <cuda_runtime.h>
#include <cuda_bf16.h>
#include <math.h>

// Problem constants
#define NN 8192
#define CH 32

// Device scratch (no allocation allowed)
__device__ __nv_bfloat16 g_H[6 * NN * CH];   // [mask(3) x part(hi/lo)(2)][8192][32] bf16 = 3 MB
__device__ float         g_P[8 * NN * CH];   // k-split partials [8][8192][32] = 8 MB
__device__ float         g_Z[NN * CH];       // layer activations [8192][32] = 1 MB
__device__ float         g_pool[64 * CH];    // per-block pooling partials

// ---------------------------------------------------------------------------
// prep: H_k = X @ w_k, split into bf16 hi + bf16 lo planes.
// grid (NN/8, 3), block 256. warp == one row j (uniform X reads), lane == c.
// ---------------------------------------------------------------------------
__global__ void prep_kernel(const float* __restrict__ X,
                            const float* __restrict__ w1,
                            const float* __restrict__ w2,
                            const float* __restrict__ w3,
                            int useZ) {
    const float* Xp = useZ ? g_Z : X;
    const int k = blockIdx.y;
    const float* w = (k == 0) ? w1 : ((k == 1) ? w2 : w3);
    const int c = threadIdx.x & 31;
    const int j = blockIdx.x * 8 + (threadIdx.x >> 5);
    const float* xr = Xp + j * CH;
    float a = 0.f;
#pragma unroll
    for (int d = 0; d < 32; d++) a += xr[d] * w[d * 32 + c];
    __nv_bfloat16 hi = __float2bfloat16(a);
    float lof = a - __bfloat162float(hi);
    __nv_bfloat16 lo = __float2bfloat16(lof);
    g_H[((k * 2 + 0) * NN + j) * CH + c] = hi;
    g_H[((k * 2 + 1) * NN + j) * CH + c] = lo;
}

// ---------------------------------------------------------------------------
// gcn: the big masked matmul. grid (64 m-tiles, 8 k-splits), 256 threads.
// Block computes rows [mtile*128, +128) x 32 cols over j-range [ksp*1024, +1024),
// writing fp32 partials to g_P[ksp]. Mask fragments built in registers from adj,
// B fragments via ldmatrix.x4.trans from smem H tiles (hi+lo planes).
// ---------------------------------------------------------------------------
__device__ __forceinline__ void mma_bf16(float* c, const unsigned* a,
                                         unsigned b0, unsigned b1) {
    asm volatile(
        "mma.sync.aligned.m16n8k16.row.col.f32.bf16.bf16.f32 "
        "{%0,%1,%2,%3},{%4,%5,%6,%7},{%8,%9},{%0,%1,%2,%3};"
        : "+f"(c[0]), "+f"(c[1]), "+f"(c[2]), "+f"(c[3])
        : "r"(a[0]), "r"(a[1]), "r"(a[2]), "r"(a[3]), "r"(b0), "r"(b1));
}

__device__ __forceinline__ void ldmx4t(unsigned& d0, unsigned& d1,
                                       unsigned& d2, unsigned& d3, unsigned addr) {
    asm volatile(
        "ldmatrix.sync.aligned.m8n8.x4.trans.shared.b16 {%0,%1,%2,%3}, [%4];"
        : "=r"(d0), "=r"(d1), "=r"(d2), "=r"(d3)
        : "r"(addr));
}

__global__ __launch_bounds__(256) void gcn_kernel(const int* __restrict__ adj) {
    __shared__ int s_adj[128 * 36];                 // 128 rows x 32 j (pad to 36)
    __shared__ __nv_bfloat16 s_H[6 * 32 * 40];      // 6 planes x 32 j x 32 c (pad to 40)

    const int tid = threadIdx.x;
    const int warp = tid >> 5, lane = tid & 31;
    const int g = lane >> 2, t = lane & 3;
    const int i0 = blockIdx.x * 128;
    const int ksp = blockIdx.y;
    const long jbase = (long)ksp * 1024;

    float acc[16];
#pragma unroll
    for (int x = 0; x < 16; x++) acc[x] = 0.f;

    const unsigned sH_base = (unsigned)__cvta_generic_to_shared(s_H);
    const unsigned lm_row = lane & 15;          // k-row within 16
    const unsigned lm_col = (lane >> 4) * 8;    // n 0 or 8
    const int r0 = warp * 16 + g;

    for (int jc = 0; jc < 1024; jc += 32) {
        __syncthreads();
        // stage adj tile: 128 x 32 int32
        {
            const int* gsrc = adj + (long)i0 * NN + jbase + jc;
#pragma unroll
            for (int q = 0; q < 4; q++) {
                int id = tid + q * 256;               // 0..1023
                int row = id >> 3, c4 = id & 7;
                int4 v = *(const int4*)(gsrc + (long)row * NN + c4 * 4);
                *(int4*)(s_adj + row * 36 + c4 * 4) = v;
            }
        }
        // stage H tiles: 6 planes x 32 j x 32 halves
        {
#pragma unroll
            for (int q = 0; q < 3; q++) {
                int id = tid + q * 256;               // 0..767
                int plane = id >> 7;
                int rem = id & 127;
                int row = rem >> 2, c4 = rem & 3;
                const __nv_bfloat16* src =
                    g_H + ((long)plane * NN + jbase + jc + row) * CH + c4 * 8;
                uint4 v = *(const uint4*)src;
                *(uint4*)(s_H + plane * 1280 + row * 40 + c4 * 8) = v;
            }
        }
        __syncthreads();

#pragma unroll
        for (int ks = 0; ks < 2; ks++) {
            // A fragments: adj -> three bf16 0/1 mask fragments, in registers
            int2 p00 = *(const int2*)(s_adj + (r0)     * 36 + ks * 16 + 2 * t);
            int2 p01 = *(const int2*)(s_adj + (r0 + 8) * 36 + ks * 16 + 2 * t);
            int2 p10 = *(const int2*)(s_adj + (r0)     * 36 + ks * 16 + 2 * t + 8);
            int2 p11 = *(const int2*)(s_adj + (r0 + 8) * 36 + ks * 16 + 2 * t + 8);
            unsigned A[3][4];
#pragma unroll
            for (int m = 0; m < 3; m++) {
                const int k = m + 1;
                A[m][0] = (p00.x == k ? 0x3F80u : 0u) | (p00.y == k ? 0x3F800000u : 0u);
                A[m][1] = (p01.x == k ? 0x3F80u : 0u) | (p01.y == k ? 0x3F800000u : 0u);
                A[m][2] = (p10.x == k ? 0x3F80u : 0u) | (p10.y == k ? 0x3F800000u : 0u);
                A[m][3] = (p11.x == k ? 0x3F80u : 0u) | (p11.y == k ? 0x3F800000u : 0u);
            }
#pragma unroll
            for (int m = 0; m < 3; m++) {
#pragma unroll
                for (int p = 0; p < 2; p++) {
                    unsigned base = sH_base +
                        (((m * 2 + p) * 32 + ks * 16 + lm_row) * 40 + lm_col) * 2;
                    unsigned b0, b1, b2, b3;
                    ldmx4t(b0, b1, b2, b3, base);          // n 0..15
                    mma_bf16(acc + 0, A[m], b0, b1);
                    mma_bf16(acc + 4, A[m], b2, b3);
                    ldmx4t(b0, b1, b2, b3, base + 32);     // n 16..31
                    mma_bf16(acc + 8, A[m], b0, b1);
                    mma_bf16(acc + 12, A[m], b2, b3);
                }
            }
        }
    }

    // write fp32 partials (deterministic; reduced in finish_kernel)
    float* P = g_P + ((long)ksp * NN + i0 + warp * 16) * CH;
#pragma unroll
    for (int nt = 0; nt < 4; nt++) {
        int c = nt * 8 + 2 * t;
        *(float2*)(P + (g)     * CH + c) = make_float2(acc[nt * 4 + 0], acc[nt * 4 + 1]);
        *(float2*)(P + (g + 8) * CH + c) = make_float2(acc[nt * 4 + 2], acc[nt * 4 + 3]);
    }
}

// ---------------------------------------------------------------------------
// finish: Z = relu(sum_s P[s] + bias); optional sum-pool partials per block.
// grid 64, block 256 (8 groups x 16 rows x 32 c).
// ---------------------------------------------------------------------------
__global__ __launch_bounds__(256) void finish_kernel(const float* __restrict__ bias,
                                                     int doPool) {
    __shared__ float red[8][32];
    const int c = threadIdx.x & 31, grp = threadIdx.x >> 5;
    const int base = blockIdx.x * 128 + grp * 16;
    const float b = bias[c];
    float local = 0.f;
    for (int r = 0; r < 16; r++) {
        const int row = base + r;
        float v = b;
#pragma unroll
        for (int s = 0; s < 8; s++) v += g_P[((long)s * NN + row) * CH + c];
        v = fmaxf(v, 0.f);
        g_Z[row * CH + c] = v;
        local += v;
    }
    if (doPool) {
        red[grp][c] = local;
        __syncthreads();
        if (grp == 0) {
            float s = 0.f;
#pragma unroll
            for (int q = 0; q < 8; q++) s += red[q][c];
            g_pool[blockIdx.x * 32 + c] = s;
        }
    }
}

// ---------------------------------------------------------------------------
// final: pool -> fc0(relu) -> fc1 -> sigmoid. 1 block, 32 threads.
// ---------------------------------------------------------------------------
__global__ void final_kernel(const float* __restrict__ fcW0, const float* __restrict__ fcb0,
                             const float* __restrict__ fcW1, const float* __restrict__ fcb1,
                             float* __restrict__ out) {
    __shared__ float pool[32];
    const int c = threadIdx.x;
    float s = 0.f;
    for (int b = 0; b < 64; b++) s += g_pool[b * 32 + c];
    pool[c] = s;
    __syncwarp();
    float o = fcb0[c];
#pragma unroll
    for (int d = 0; d < 32; d++) o += pool[d] * fcW0[c * 32 + d];
    o = fmaxf(o, 0.f);
    float v = o * fcW1[c];
#pragma unroll
    for (int off = 16; off; off >>= 1) v += __shfl_xor_sync(0xffffffffu, v, off);
    if (c == 0) out[0] = 1.f / (1.f + expf(-(v + fcb1[0])));
}

// ---------------------------------------------------------------------------
extern "C" void kernel_launch(void* const* d_in, const int* in_sizes, int n_in,
                              void* d_out, int out_size) {
    (void)in_sizes; (void)n_in; (void)out_size;
    const float* V    = (const float*)d_in[0];
    const int*   adj  = (const int*)d_in[1];
    const float* w1_0 = (const float*)d_in[2];
    const float* w2_0 = (const float*)d_in[3];
    const float* w3_0 = (const float*)d_in[4];
    const float* gb_0 = (const float*)d_in[5];
    const float* w1_1 = (const float*)d_in[6];
    const float* w2_1 = (const float*)d_in[7];
    const float* w3_1 = (const float*)d_in[8];
    const float* gb_1 = (const float*)d_in[9];
    const float* fcW0 = (const float*)d_in[10];
    const float* fcb0 = (const float*)d_in[11];
    const float* fcW1 = (const float*)d_in[12];
    const float* fcb1 = (const float*)d_in[13];

    dim3 gP(NN / 8, 3);
    dim3 gG(64, 8);

    // Layer 1
    prep_kernel<<<gP, 256>>>(V, w1_0, w2_0, w3_0, 0);
    gcn_kernel<<<gG, 256>>>(adj);
    finish_kernel<<<64, 256>>>(gb_0, 0);
    // Layer 2
    prep_kernel<<<gP, 256>>>(V, w1_1, w2_1, w3_1, 1);
    gcn_kernel<<<gG, 256>>>(adj);
    finish_kernel<<<64, 256>>>(gb_1, 1);
    // Head
    final_kernel<<<1, 32>>>(fcW0, fcb0, fcW1, fcb1, (float*)d_out);
}

// round 5
// speedup vs baseline: 1.4982x; 1.4982x over previous
#include <cuda_runtime.h>
#include <cuda_bf16.h>
#include <math.h>

// Problem constants
#define NN 8192
#define CH 32

// Device scratch (no allocation allowed)
__device__ __align__(256) __nv_bfloat16 g_H[3 * NN * CH];  // [mask k][8192][32] bf16, 1.5 MB
__device__ float g_P[8 * NN * CH];   // k-split partials [8][8192][32] = 8 MB
__device__ float g_Z[NN * CH];       // layer activations
__device__ float g_pool[64 * CH];    // per-block pooling partials

// ---------------------------------------------------------------------------
// prep: H_k = X @ w_k (single bf16 plane). Weights staged in smem, 32 rows/block.
// ---------------------------------------------------------------------------
__global__ __launch_bounds__(256) void prep_kernel(const float* __restrict__ X,
                                                   const float* __restrict__ w1,
                                                   const float* __restrict__ w2,
                                                   const float* __restrict__ w3,
                                                   int useZ) {
    __shared__ float sw[3][32][32];  // [k][d][c]
    const float* Xp = useZ ? g_Z : X;
    const int tid = threadIdx.x;
#pragma unroll
    for (int k = 0; k < 3; k++) {
        const float* wp = (k == 0) ? w1 : ((k == 1) ? w2 : w3);
#pragma unroll
        for (int q = 0; q < 4; q++) {
            int id = tid + q * 256;                 // 0..1023
            sw[k][id >> 5][id & 31] = wp[id];
        }
    }
    __syncthreads();
    const int c = tid & 31, warp = tid >> 5;
#pragma unroll
    for (int rr = 0; rr < 4; rr++) {
        const int j = blockIdx.x * 32 + warp * 4 + rr;
        const float* xr = Xp + (long)j * CH;
        float x[32];
#pragma unroll
        for (int d = 0; d < 32; d++) x[d] = xr[d];
#pragma unroll
        for (int k = 0; k < 3; k++) {
            float a = 0.f;
#pragma unroll
            for (int d = 0; d < 32; d++) a += x[d] * sw[k][d][c];
            g_H[((long)k * NN + j) * CH + c] = __float2bfloat16(a);
        }
    }
}

// ---------------------------------------------------------------------------
// gcn: masked matmul. grid (64 m-tiles, 8 k-splits), 256 threads (8 warps x 16 rows).
// adj fragments loaded DIRECTLY from global as int2 (exact MMA layout, no smem).
// Three bf16 0/1 mask A-words built with a single PRMT each via a LUT selector.
// H staged per 128-j superblock; B frags via ldmatrix.x4.trans.
// ---------------------------------------------------------------------------
__device__ __forceinline__ void mma_bf16(float* c, const unsigned* a,
                                         unsigned b0, unsigned b1) {
    asm volatile(
        "mma.sync.aligned.m16n8k16.row.col.f32.bf16.bf16.f32 "
        "{%0,%1,%2,%3},{%4,%5,%6,%7},{%8,%9},{%0,%1,%2,%3};"
        : "+f"(c[0]), "+f"(c[1]), "+f"(c[2]), "+f"(c[3])
        : "r"(a[0]), "r"(a[1]), "r"(a[2]), "r"(a[3]), "r"(b0), "r"(b1));
}

__device__ __forceinline__ void ldmx4t(unsigned& d0, unsigned& d1,
                                       unsigned& d2, unsigned& d3, unsigned addr) {
    asm volatile(
        "ldmatrix.sync.aligned.m8n8.x4.trans.shared.b16 {%0,%1,%2,%3}, [%4];"
        : "=r"(d0), "=r"(d1), "=r"(d2), "=r"(d3)
        : "r"(addr));
}

__global__ __launch_bounds__(256) void gcn_kernel(const int* __restrict__ adj) {
    __shared__ __align__(16) __nv_bfloat16 s_H[3 * 128 * 40];  // 3 planes x 128 j x 32 c (pad 40)

    const int tid = threadIdx.x;
    const int warp = tid >> 5, lane = tid & 31;
    const int g = lane >> 2, t = lane & 3;
    const int i0 = blockIdx.x * 128;
    const int ksp = blockIdx.y;
    const long jbase = (long)ksp * 1024;

    float acc[16];
#pragma unroll
    for (int x = 0; x < 16; x++) acc[x] = 0.f;

    const unsigned sH_base = (unsigned)__cvta_generic_to_shared(s_H);
    const unsigned lm_row = lane & 15;
    const unsigned lm_col = (lane >> 4) * 8;
    const int r0 = i0 + warp * 16 + g;
    const int* arow0 = adj + (long)r0 * NN + jbase + 2 * t;  // row g
    const int* arow1 = arow0 + 8L * NN;                      // row g+8

    for (int jsb = 0; jsb < 1024; jsb += 128) {
        __syncthreads();
        // stage H superblock: 3 planes x 128 j x 32 c bf16 = 24 KB, coalesced uint4
#pragma unroll
        for (int q = 0; q < 6; q++) {
            int id = tid + q * 256;                 // 0..1535
            int plane = id >> 9;
            int rem = id & 511;
            int row = rem >> 2, c4 = rem & 3;
            const __nv_bfloat16* src =
                g_H + ((long)plane * NN + jbase + jsb + row) * CH + c4 * 8;
            *(uint4*)(s_H + (plane * 128 + row) * 40 + c4 * 8) = *(const uint4*)src;
        }
        __syncthreads();

#pragma unroll
        for (int jo = 0; jo < 128; jo += 32) {
#pragma unroll
            for (int ks = 0; ks < 2; ks++) {
                const int cb = jsb + jo + ks * 16;
                int2 p00 = *(const int2*)(arow0 + cb);      // row g,   cols 2t..2t+1
                int2 p01 = *(const int2*)(arow1 + cb);      // row g+8
                int2 p10 = *(const int2*)(arow0 + cb + 8);  // row g,   cols 2t+8..
                int2 p11 = *(const int2*)(arow1 + cb + 8);

                // PRMT-LUT mask build: sel nibbles {v0, v0+4, v1, v1+4}
                unsigned A1[4], A2[4], A3[4];
#define MK(P, i)                                                              \
                {                                                             \
                    unsigned s0 = (unsigned)(P).x + ((unsigned)(P).y << 8);   \
                    unsigned sel = s0 * 0x11u + 0x4040u;                      \
                    A1[i] = __byte_perm(0x00008000u, 0x00003F00u, sel);       \
                    A2[i] = __byte_perm(0x00800000u, 0x003F0000u, sel);       \
                    A3[i] = __byte_perm(0x80000000u, 0x3F000000u, sel);       \
                }
                MK(p00, 0) MK(p01, 1) MK(p10, 2) MK(p11, 3)
#undef MK

#pragma unroll
                for (int m = 0; m < 3; m++) {
                    const unsigned* Am = (m == 0) ? A1 : ((m == 1) ? A2 : A3);
                    unsigned base = sH_base +
                        (((unsigned)(m * 128 + jo) + ks * 16 + lm_row) * 40 + lm_col) * 2;
                    unsigned b0, b1, b2, b3;
                    ldmx4t(b0, b1, b2, b3, base);          // n 0..15
                    mma_bf16(acc + 0, Am, b0, b1);
                    mma_bf16(acc + 4, Am, b2, b3);
                    ldmx4t(b0, b1, b2, b3, base + 32);     // n 16..31
                    mma_bf16(acc + 8, Am, b0, b1);
                    mma_bf16(acc + 12, Am, b2, b3);
                }
            }
        }
    }

    // write fp32 partials (deterministic; reduced in finish_kernel)
    float* P = g_P + ((long)ksp * NN + i0 + warp * 16) * CH;
#pragma unroll
    for (int nt = 0; nt < 4; nt++) {
        int c = nt * 8 + 2 * t;
        *(float2*)(P + (g)     * CH + c) = make_float2(acc[nt * 4 + 0], acc[nt * 4 + 1]);
        *(float2*)(P + (g + 8) * CH + c) = make_float2(acc[nt * 4 + 2], acc[nt * 4 + 3]);
    }
}

// ---------------------------------------------------------------------------
// finish: Z = relu(sum_s P[s] + bias); optional sum-pool partials per block.
// ---------------------------------------------------------------------------
__global__ __launch_bounds__(256) void finish_kernel(const float* __restrict__ bias,
                                                     int doPool) {
    __shared__ float red[8][32];
    const int c = threadIdx.x & 31, grp = threadIdx.x >> 5;
    const int base = blockIdx.x * 128 + grp * 16;
    const float b = bias[c];
    float local = 0.f;
    for (int r = 0; r < 16; r++) {
        const int row = base + r;
        float v = b;
#pragma unroll
        for (int s = 0; s < 8; s++) v += g_P[((long)s * NN + row) * CH + c];
        v = fmaxf(v, 0.f);
        g_Z[row * CH + c] = v;
        local += v;
    }
    if (doPool) {
        red[grp][c] = local;
        __syncthreads();
        if (grp == 0) {
            float s = 0.f;
#pragma unroll
            for (int q = 0; q < 8; q++) s += red[q][c];
            g_pool[blockIdx.x * 32 + c] = s;
        }
    }
}

// ---------------------------------------------------------------------------
// final: pool -> fc0(relu) -> fc1 -> sigmoid. 1 block, 32 threads.
// ---------------------------------------------------------------------------
__global__ void final_kernel(const float* __restrict__ fcW0, const float* __restrict__ fcb0,
                             const float* __restrict__ fcW1, const float* __restrict__ fcb1,
                             float* __restrict__ out) {
    __shared__ float pool[32];
    const int c = threadIdx.x;
    float s = 0.f;
    for (int b = 0; b < 64; b++) s += g_pool[b * 32 + c];
    pool[c] = s;
    __syncwarp();
    float o = fcb0[c];
#pragma unroll
    for (int d = 0; d < 32; d++) o += pool[d] * fcW0[c * 32 + d];
    o = fmaxf(o, 0.f);
    float v = o * fcW1[c];
#pragma unroll
    for (int off = 16; off; off >>= 1) v += __shfl_xor_sync(0xffffffffu, v, off);
    if (c == 0) out[0] = 1.f / (1.f + expf(-(v + fcb1[0])));
}

// ---------------------------------------------------------------------------
extern "C" void kernel_launch(void* const* d_in, const int* in_sizes, int n_in,
                              void* d_out, int out_size) {
    (void)in_sizes; (void)n_in; (void)out_size;
    const float* V    = (const float*)d_in[0];
    const int*   adj  = (const int*)d_in[1];
    const float* w1_0 = (const float*)d_in[2];
    const float* w2_0 = (const float*)d_in[3];
    const float* w3_0 = (const float*)d_in[4];
    const float* gb_0 = (const float*)d_in[5];
    const float* w1_1 = (const float*)d_in[6];
    const float* w2_1 = (const float*)d_in[7];
    const float* w3_1 = (const float*)d_in[8];
    const float* gb_1 = (const float*)d_in[9];
    const float* fcW0 = (const float*)d_in[10];
    const float* fcb0 = (const float*)d_in[11];
    const float* fcW1 = (const float*)d_in[12];
    const float* fcb1 = (const float*)d_in[13];

    dim3 gG(64, 8);

    // Layer 1
    prep_kernel<<<256, 256>>>(V, w1_0, w2_0, w3_0, 0);
    gcn_kernel<<<gG, 256>>>(adj);
    finish_kernel<<<64, 256>>>(gb_0, 0);
    // Layer 2
    prep_kernel<<<256, 256>>>(V, w1_1, w2_1, w3_1, 1);
    gcn_kernel<<<gG, 256>>>(adj);
    finish_kernel<<<64, 256>>>(gb_1, 1);
    // Head
    final_kernel<<<1, 32>>>(fcW0, fcb0, fcW1, fcb1, (float*)d_out);
}

// round 6
// speedup vs baseline: 1.5617x; 1.0424x over previous
#include <cuda_runtime.h>
#include <cuda_bf16.h>
#include <math.h>

// Problem constants
#define NN 8192
#define CH 32
#define NP (NN / 16)   // packed u32 per row = 512

// Device scratch (no allocation allowed)
__device__ __align__(256) unsigned g_A[(long)NN * NP];         // 2-bit packed adj, 16 MB
__device__ __align__(256) __nv_bfloat16 g_H[3 * NN * CH];      // [mask k][8192][32] bf16
__device__ float g_P[8 * NN * CH];                             // k-split partials, 8 MB
__device__ float g_pool[64 * CH];                              // per-block pooling partials

// ---------------------------------------------------------------------------
// repack: adj int32 -> 2-bit packed. One u32 per thread (16 entries).
// ---------------------------------------------------------------------------
__global__ __launch_bounds__(256) void repack_kernel(const int* __restrict__ adj) {
    const long idx = (long)blockIdx.x * 256 + threadIdx.x;     // 0 .. 4M-1
    const int4* src = (const int4*)(adj + idx * 16);
    unsigned w = 0;
#pragma unroll
    for (int q = 0; q < 4; q++) {
        int4 a = src[q];
        unsigned b = (unsigned)(a.x & 3) | ((unsigned)(a.y & 3) << 2) |
                     ((unsigned)(a.z & 3) << 4) | ((unsigned)(a.w & 3) << 6);
        w |= b << (q * 8);
    }
    g_A[idx] = w;
}

// ---------------------------------------------------------------------------
// shared helper: H_k[row][c] = sum_d z_d * w_k[d][c], z held one-element-per-lane.
// ---------------------------------------------------------------------------
__device__ __forceinline__ void row_to_H(float z, int row, int c,
                                         const float (*sw)[32][32]) {
    float a0 = 0.f, a1 = 0.f, a2 = 0.f;
#pragma unroll
    for (int d = 0; d < 32; d++) {
        float zd = __shfl_sync(0xffffffffu, z, d);
        a0 += zd * sw[0][d][c];
        a1 += zd * sw[1][d][c];
        a2 += zd * sw[2][d][c];
    }
    g_H[((long)0 * NN + row) * CH + c] = __float2bfloat16(a0);
    g_H[((long)1 * NN + row) * CH + c] = __float2bfloat16(a1);
    g_H[((long)2 * NN + row) * CH + c] = __float2bfloat16(a2);
}

__device__ __forceinline__ void stage_weights(float (*sw)[32][32],
                                              const float* __restrict__ w1,
                                              const float* __restrict__ w2,
                                              const float* __restrict__ w3,
                                              int tid) {
#pragma unroll
    for (int q = 0; q < 4; q++) {
        int id = tid + q * 256;
        sw[0][id >> 5][id & 31] = w1[id];
        sw[1][id >> 5][id & 31] = w2[id];
        sw[2][id >> 5][id & 31] = w3[id];
    }
}

// ---------------------------------------------------------------------------
// prep1: H_k = V @ w_k. Warp per row, grid 1024 x 256 threads.
// ---------------------------------------------------------------------------
__global__ __launch_bounds__(256) void prep1_kernel(const float* __restrict__ V,
                                                    const float* __restrict__ w1,
                                                    const float* __restrict__ w2,
                                                    const float* __restrict__ w3) {
    __shared__ float sw[3][32][32];
    const int tid = threadIdx.x;
    stage_weights(sw, w1, w2, w3, tid);
    __syncthreads();
    const int c = tid & 31, warp = tid >> 5;
    const int row = blockIdx.x * 8 + warp;
    float z = V[(long)row * CH + c];
    row_to_H(z, row, c, sw);
}

// ---------------------------------------------------------------------------
// finishprep: Z = relu(sum_s P[s] + gb0) (not stored), then H_k = Z @ w_k(layer2).
// grid 64 x 256 (8 warps x 16 rows each).
// ---------------------------------------------------------------------------
__global__ __launch_bounds__(256) void finishprep_kernel(const float* __restrict__ bias,
                                                         const float* __restrict__ w1,
                                                         const float* __restrict__ w2,
                                                         const float* __restrict__ w3) {
    __shared__ float sw[3][32][32];
    const int tid = threadIdx.x;
    stage_weights(sw, w1, w2, w3, tid);
    __syncthreads();
    const int c = tid & 31, warp = tid >> 5;
    const int base = blockIdx.x * 128 + warp * 16;
    const float b = bias[c];
    for (int r = 0; r < 16; r++) {
        const int row = base + r;
        float v = b;
#pragma unroll
        for (int s = 0; s < 8; s++) v += g_P[((long)s * NN + row) * CH + c];
        v = fmaxf(v, 0.f);
        row_to_H(v, row, c, sw);
    }
}

// ---------------------------------------------------------------------------
// gcn: masked matmul from packed adj + bf16 H. grid (64, 8), 256 threads.
// ---------------------------------------------------------------------------
__device__ __forceinline__ void mma_bf16(float* c, const unsigned* a,
                                         unsigned b0, unsigned b1) {
    asm volatile(
        "mma.sync.aligned.m16n8k16.row.col.f32.bf16.bf16.f32 "
        "{%0,%1,%2,%3},{%4,%5,%6,%7},{%8,%9},{%0,%1,%2,%3};"
        : "+f"(c[0]), "+f"(c[1]), "+f"(c[2]), "+f"(c[3])
        : "r"(a[0]), "r"(a[1]), "r"(a[2]), "r"(a[3]), "r"(b0), "r"(b1));
}

__device__ __forceinline__ void ldmx4t(unsigned& d0, unsigned& d1,
                                       unsigned& d2, unsigned& d3, unsigned addr) {
    asm volatile(
        "ldmatrix.sync.aligned.m8n8.x4.trans.shared.b16 {%0,%1,%2,%3}, [%4];"
        : "=r"(d0), "=r"(d1), "=r"(d2), "=r"(d3)
        : "r"(addr));
}

__global__ __launch_bounds__(256) void gcn_kernel() {
    __shared__ __align__(16) __nv_bfloat16 s_H[3 * 128 * 40];  // 3 planes x 128 j x 32 c (pad 40)

    const int tid = threadIdx.x;
    const int warp = tid >> 5, lane = tid & 31;
    const int g = lane >> 2, t = lane & 3;
    const int i0 = blockIdx.x * 128;
    const int ksp = blockIdx.y;
    const long jbase = (long)ksp * 1024;

    float acc[16];
#pragma unroll
    for (int x = 0; x < 16; x++) acc[x] = 0.f;

    const unsigned sH_base = (unsigned)__cvta_generic_to_shared(s_H);
    const unsigned lm_row = lane & 15;
    const unsigned lm_col = (lane >> 4) * 8;
    const int r0 = i0 + warp * 16 + g;
    const unsigned* ap0 = g_A + (long)r0 * NP + jbase / 16;   // row g
    const unsigned* ap1 = ap0 + 8L * NP;                      // row g+8

    for (int jsb = 0; jsb < 1024; jsb += 128) {
        __syncthreads();
        // stage H superblock: 3 planes x 128 j x 32 c bf16 = 24 KB
#pragma unroll
        for (int q = 0; q < 6; q++) {
            int id = tid + q * 256;
            int plane = id >> 9;
            int rem = id & 511;
            int row = rem >> 2, c4 = rem & 3;
            const __nv_bfloat16* src =
                g_H + ((long)plane * NN + jbase + jsb + row) * CH + c4 * 8;
            *(uint4*)(s_H + (plane * 128 + row) * 40 + c4 * 8) = *(const uint4*)src;
        }
        __syncthreads();

#pragma unroll
        for (int jo = 0; jo < 128; jo += 32) {
            const int jc = jsb + jo;
            const uint2 wg = *(const uint2*)(ap0 + (jc >> 4));   // row g,   32 cols
            const uint2 wh = *(const uint2*)(ap1 + (jc >> 4));   // row g+8, 32 cols
#pragma unroll
            for (int ks = 0; ks < 2; ks++) {
                const unsigned pg = ks ? wg.y : wg.x;
                const unsigned ph = ks ? wh.y : wh.x;
                // nibble extraction: entries (2t,2t+1) at bit 4t; (2t+8,2t+9) at 16+4t
                unsigned e0 = (pg >> (4 * t)) & 0xFu;        // row g,   low cols
                unsigned e1 = (ph >> (4 * t)) & 0xFu;        // row g+8, low cols
                unsigned e2 = (pg >> (16 + 4 * t)) & 0xFu;   // row g,   high cols
                unsigned e3 = (ph >> (16 + 4 * t)) & 0xFu;   // row g+8, high cols

                unsigned A1[4], A2[4], A3[4];
#define MK(E, i)                                                              \
                {                                                             \
                    unsigned sel = ((E) & 3u) * 0x11u + ((E) >> 2) * 0x1100u + 0x4040u; \
                    A1[i] = __byte_perm(0x00008000u, 0x00003F00u, sel);       \
                    A2[i] = __byte_perm(0x00800000u, 0x003F0000u, sel);       \
                    A3[i] = __byte_perm(0x80000000u, 0x3F000000u, sel);       \
                }
                MK(e0, 0) MK(e1, 1) MK(e2, 2) MK(e3, 3)
#undef MK

#pragma unroll
                for (int m = 0; m < 3; m++) {
                    const unsigned* Am = (m == 0) ? A1 : ((m == 1) ? A2 : A3);
                    unsigned base = sH_base +
                        (((unsigned)(m * 128 + jo) + ks * 16 + lm_row) * 40 + lm_col) * 2;
                    unsigned b0, b1, b2, b3;
                    ldmx4t(b0, b1, b2, b3, base);          // n 0..15
                    mma_bf16(acc + 0, Am, b0, b1);
                    mma_bf16(acc + 4, Am, b2, b3);
                    ldmx4t(b0, b1, b2, b3, base + 32);     // n 16..31
                    mma_bf16(acc + 8, Am, b0, b1);
                    mma_bf16(acc + 12, Am, b2, b3);
                }
            }
        }
    }

    // fp32 partials (deterministic; reduced downstream)
    float* P = g_P + ((long)ksp * NN + i0 + warp * 16) * CH;
#pragma unroll
    for (int nt = 0; nt < 4; nt++) {
        int c = nt * 8 + 2 * t;
        *(float2*)(P + (g)     * CH + c) = make_float2(acc[nt * 4 + 0], acc[nt * 4 + 1]);
        *(float2*)(P + (g + 8) * CH + c) = make_float2(acc[nt * 4 + 2], acc[nt * 4 + 3]);
    }
}

// ---------------------------------------------------------------------------
// finish2: pooled sums of relu(sum_s P[s] + gb1). grid 64 x 256.
// ---------------------------------------------------------------------------
__global__ __launch_bounds__(256) void finish2_kernel(const float* __restrict__ bias) {
    __shared__ float red[8][32];
    const int c = threadIdx.x & 31, grp = threadIdx.x >> 5;
    const int base = blockIdx.x * 128 + grp * 16;
    const float b = bias[c];
    float local = 0.f;
    for (int r = 0; r < 16; r++) {
        const int row = base + r;
        float v = b;
#pragma unroll
        for (int s = 0; s < 8; s++) v += g_P[((long)s * NN + row) * CH + c];
        local += fmaxf(v, 0.f);
    }
    red[grp][c] = local;
    __syncthreads();
    if (grp == 0) {
        float s = 0.f;
#pragma unroll
        for (int q = 0; q < 8; q++) s += red[q][c];
        g_pool[blockIdx.x * 32 + c] = s;
    }
}

// ---------------------------------------------------------------------------
// final: pool -> fc0(relu) -> fc1 -> sigmoid. 1 block, 32 threads.
// ---------------------------------------------------------------------------
__global__ void final_kernel(const float* __restrict__ fcW0, const float* __restrict__ fcb0,
                             const float* __restrict__ fcW1, const float* __restrict__ fcb1,
                             float* __restrict__ out) {
    __shared__ float pool[32];
    const int c = threadIdx.x;
    float s = 0.f;
    for (int b = 0; b < 64; b++) s += g_pool[b * 32 + c];
    pool[c] = s;
    __syncwarp();
    float o = fcb0[c];
#pragma unroll
    for (int d = 0; d < 32; d++) o += pool[d] * fcW0[c * 32 + d];
    o = fmaxf(o, 0.f);
    float v = o * fcW1[c];
#pragma unroll
    for (int off = 16; off; off >>= 1) v += __shfl_xor_sync(0xffffffffu, v, off);
    if (c == 0) out[0] = 1.f / (1.f + expf(-(v + fcb1[0])));
}

// ---------------------------------------------------------------------------
extern "C" void kernel_launch(void* const* d_in, const int* in_sizes, int n_in,
                              void* d_out, int out_size) {
    (void)in_sizes; (void)n_in; (void)out_size;
    const float* V    = (const float*)d_in[0];
    const int*   adj  = (const int*)d_in[1];
    const float* w1_0 = (const float*)d_in[2];
    const float* w2_0 = (const float*)d_in[3];
    const float* w3_0 = (const float*)d_in[4];
    const float* gb_0 = (const float*)d_in[5];
    const float* w1_1 = (const float*)d_in[6];
    const float* w2_1 = (const float*)d_in[7];
    const float* w3_1 = (const float*)d_in[8];
    const float* gb_1 = (const float*)d_in[9];
    const float* fcW0 = (const float*)d_in[10];
    const float* fcb0 = (const float*)d_in[11];
    const float* fcW1 = (const float*)d_in[12];
    const float* fcb1 = (const float*)d_in[13];

    dim3 gG(64, 8);

    repack_kernel<<<NN * NP / 256, 256>>>(adj);              // adj -> 2-bit packed
    prep1_kernel<<<1024, 256>>>(V, w1_0, w2_0, w3_0);        // H for layer 1
    gcn_kernel<<<gG, 256>>>();                               // layer-1 masked matmul
    finishprep_kernel<<<64, 256>>>(gb_0, w1_1, w2_1, w3_1);  // relu+bias, H for layer 2
    gcn_kernel<<<gG, 256>>>();                               // layer-2 masked matmul
    finish2_kernel<<<64, 256>>>(gb_1);                       // relu+bias+pool
    final_kernel<<<1, 32>>>(fcW0, fcb0, fcW1, fcb1, (float*)d_out);
}